// round 1
// baseline (speedup 1.0000x reference)
#include <cuda_runtime.h>

// Problem constants (fixed shapes from setup_inputs)
#define LQ 512   // sequence length
#define DD 256   // per-tensor feature dim
#define FD 512   // 2*DD (MLP hidden)
#define NB 2     // batch
#define NH 8     // heads
#define DK 64    // head dim

// Scratch (no cudaMalloc allowed) — 6 MB total
__device__ float g_A[NB * LQ * FD];   // d1 @ W1[:DD]
__device__ float g_C[NB * LQ * FD];   // d0 @ W1[DD:] + b1
__device__ float g_D[NB * LQ * LQ];   // decisions: 0 or -1e9

// ---------------------------------------------------------------------------
// Kernel 1: A = d1 @ W1_top, C = d0 @ W1_bot + b1
// M = NB*LQ = 1024 rows, N = FD = 512, K = DD = 256. blockIdx.z selects A/C.
// 64x64 tile, 256 threads, 4x4 per thread, K-chunk 32.
// ---------------------------------------------------------------------------
__global__ __launch_bounds__(256) void gemm_ac_kernel(
    const float* __restrict__ d1, const float* __restrict__ d0,
    const float* __restrict__ W1, const float* __restrict__ b1)
{
    const int z = blockIdx.z;                       // 0 -> A, 1 -> C
    const float* src = z ? d0 : d1;                 // [1024, 256]
    const float* W   = W1 + (z ? (size_t)DD * FD : 0);  // [256, 512]
    float* dst = z ? g_C : g_A;

    __shared__ float As[64][33];   // [m][k], pad breaks stride-128 bank repeat
    __shared__ float Bs[32][64];   // [k][n]

    const int m0 = blockIdx.y * 64;
    const int n0 = blockIdx.x * 64;
    const int t  = threadIdx.x;
    const int tx = t & 15, ty = t >> 4;

    float acc[4][4] = {};

    for (int k0 = 0; k0 < DD; k0 += 32) {
        // src tile: 64 rows x 32 k, coalesced (32 floats = 128B per row)
        #pragma unroll
        for (int r = 0; r < 8; r++) {
            int lin = t + r * 256;
            int mm = lin >> 5, kk = lin & 31;
            As[mm][kk] = src[(size_t)(m0 + mm) * DD + k0 + kk];
        }
        // W tile: 32 k x 64 n, coalesced
        #pragma unroll
        for (int r = 0; r < 8; r++) {
            int lin = t + r * 256;
            int kk = lin >> 6, nn = lin & 63;
            Bs[kk][nn] = W[(size_t)(k0 + kk) * FD + n0 + nn];
        }
        __syncthreads();

        #pragma unroll
        for (int kk = 0; kk < 32; kk++) {
            float a[4], b[4];
            #pragma unroll
            for (int i = 0; i < 4; i++) a[i] = As[ty * 4 + i][kk];
            #pragma unroll
            for (int j = 0; j < 4; j++) b[j] = Bs[kk][tx * 4 + j];
            #pragma unroll
            for (int i = 0; i < 4; i++)
                #pragma unroll
                for (int j = 0; j < 4; j++)
                    acc[i][j] = fmaf(a[i], b[j], acc[i][j]);
        }
        __syncthreads();
    }

    #pragma unroll
    for (int i = 0; i < 4; i++) {
        int m = m0 + ty * 4 + i;
        #pragma unroll
        for (int j = 0; j < 4; j++) {
            int n = n0 + tx * 4 + j;
            float v = acc[i][j];
            if (z) v += b1[n];          // fold b1 into C
            dst[(size_t)m * FD + n] = v;
        }
    }
}

// ---------------------------------------------------------------------------
// Kernel 2: decisions[b,i,j] = (sum_f relu(A[b,i,f]+C[b,j,f]) * w2d[f] + b2d > 0)
//           ? -1e9 : 0
// Per batch: 512x512 output, 512 reduction. 64x64 tile, 256 threads, 4x4/thread.
// Two-level accumulation (per 32-chunk partials) to keep rounding error ~1e-7.
// ---------------------------------------------------------------------------
__global__ __launch_bounds__(256) void decisions_kernel(
    const float* __restrict__ W2, const float* __restrict__ b2)
{
    const int b  = blockIdx.z;
    const int i0 = blockIdx.y * 64;
    const int j0 = blockIdx.x * 64;
    const float* Ab = g_A + (size_t)b * LQ * FD;
    const float* Cb = g_C + (size_t)b * LQ * FD;

    __shared__ float As[64][33];   // [i][f-chunk]
    __shared__ float Cs[64][33];   // [j][f-chunk]
    __shared__ float ws[FD];       // W2[:,1]-W2[:,0], loaded once

    const int t  = threadIdx.x;
    const int tx = t & 15, ty = t >> 4;

    // load w2 diff once
    for (int f = t; f < FD; f += 256)
        ws[f] = W2[f * 2 + 1] - W2[f * 2 + 0];

    float acc[4][4] = {};

    for (int f0 = 0; f0 < FD; f0 += 32) {
        __syncthreads();
        #pragma unroll
        for (int r = 0; r < 8; r++) {
            int lin = t + r * 256;
            int mm = lin >> 5, ff = lin & 31;
            As[mm][ff] = Ab[(size_t)(i0 + mm) * FD + f0 + ff];
            Cs[mm][ff] = Cb[(size_t)(j0 + mm) * FD + f0 + ff];
        }
        __syncthreads();

        float accC[4][4] = {};     // chunk-local partial (accuracy)
        #pragma unroll
        for (int ff = 0; ff < 32; ff++) {
            float w = ws[f0 + ff];
            float a[4], c[4];
            #pragma unroll
            for (int i = 0; i < 4; i++) a[i] = As[ty * 4 + i][ff];
            #pragma unroll
            for (int j = 0; j < 4; j++) c[j] = Cs[tx * 4 + j][ff];
            #pragma unroll
            for (int i = 0; i < 4; i++)
                #pragma unroll
                for (int j = 0; j < 4; j++) {
                    float h = fmaxf(a[i] + c[j], 0.0f);
                    accC[i][j] = fmaf(h, w, accC[i][j]);
                }
        }
        #pragma unroll
        for (int i = 0; i < 4; i++)
            #pragma unroll
            for (int j = 0; j < 4; j++)
                acc[i][j] += accC[i][j];
    }

    const float b2d = b2[1] - b2[0];
    float* Db = g_D + (size_t)b * LQ * LQ;
    #pragma unroll
    for (int i = 0; i < 4; i++) {
        int ii = i0 + ty * 4 + i;
        #pragma unroll
        for (int j = 0; j < 4; j++) {
            int jj = j0 + tx * 4 + j;
            // strict > matches argmax tie-break to index 0; Sterbenz makes the
            // straight-through value exactly 1 (or 0), so the mask is exact.
            Db[(size_t)ii * LQ + jj] = (acc[i][j] + b2d > 0.0f) ? -1e9f : 0.0f;
        }
    }
}

// ---------------------------------------------------------------------------
// Kernel 3: out[b,n,i,j] = dot(q[b,n,i,:], k[b,n,j,:]) / 8 + D[b,i,j]
// 64x64 tile per (b,n), full K=64 staged in smem, 4x4 per thread.
// ---------------------------------------------------------------------------
__global__ __launch_bounds__(256) void attn_kernel(
    const float* __restrict__ q, const float* __restrict__ k,
    float* __restrict__ out)
{
    const int bn = blockIdx.z;          // 0..15 = b*NH + n
    const int b  = bn >> 3;
    const int i0 = blockIdx.y * 64;
    const int j0 = blockIdx.x * 64;
    const float* Q = q + (size_t)bn * LQ * DK;
    const float* K = k + (size_t)bn * LQ * DK;

    __shared__ float Qs[64][65];
    __shared__ float Ks[64][65];

    const int t  = threadIdx.x;
    const int tx = t & 15, ty = t >> 4;

    #pragma unroll
    for (int r = 0; r < 16; r++) {
        int lin = t + r * 256;
        int ii = lin >> 6, dd = lin & 63;
        Qs[ii][dd] = Q[(size_t)(i0 + ii) * DK + dd];
        Ks[ii][dd] = K[(size_t)(j0 + ii) * DK + dd];
    }
    __syncthreads();

    float acc[4][4] = {};
    #pragma unroll 16
    for (int dd = 0; dd < DK; dd++) {
        float a[4], c[4];
        #pragma unroll
        for (int i = 0; i < 4; i++) a[i] = Qs[ty * 4 + i][dd];
        #pragma unroll
        for (int j = 0; j < 4; j++) c[j] = Ks[tx * 4 + j][dd];
        #pragma unroll
        for (int i = 0; i < 4; i++)
            #pragma unroll
            for (int j = 0; j < 4; j++)
                acc[i][j] = fmaf(a[i], c[j], acc[i][j]);
    }

    const float* Db = g_D + (size_t)b * LQ * LQ;
    float* O = out + (size_t)bn * LQ * LQ;
    #pragma unroll
    for (int i = 0; i < 4; i++) {
        int ii = i0 + ty * 4 + i;
        #pragma unroll
        for (int j = 0; j < 4; j++) {
            int jj = j0 + tx * 4 + j;
            O[(size_t)ii * LQ + jj] =
                acc[i][j] * 0.125f + Db[(size_t)ii * LQ + jj];
        }
    }
}

// ---------------------------------------------------------------------------
// Inputs (metadata order): q, k, d0, d1, W1, b1, W2, b2
// ---------------------------------------------------------------------------
extern "C" void kernel_launch(void* const* d_in, const int* in_sizes, int n_in,
                              void* d_out, int out_size)
{
    const float* q  = (const float*)d_in[0];   // [2,8,512,64]
    const float* k  = (const float*)d_in[1];   // [2,8,512,64]
    const float* d0 = (const float*)d_in[2];   // [2,512,256]
    const float* d1 = (const float*)d_in[3];   // [2,512,256]
    const float* W1 = (const float*)d_in[4];   // [512,512]
    const float* b1 = (const float*)d_in[5];   // [512]
    const float* W2 = (const float*)d_in[6];   // [512,2]
    const float* b2 = (const float*)d_in[7];   // [2]
    float* out = (float*)d_out;                // [2,8,512,512]

    (void)in_sizes; (void)n_in; (void)out_size;

    // 1) A and C projections (z=0 -> A from d1, z=1 -> C from d0 + b1)
    {
        dim3 grid(FD / 64, (NB * LQ) / 64, 2);   // (8, 16, 2)
        gemm_ac_kernel<<<grid, 256>>>(d1, d0, W1, b1);
    }
    // 2) decision mask
    {
        dim3 grid(LQ / 64, LQ / 64, NB);         // (8, 8, 2)
        decisions_kernel<<<grid, 256>>>(W2, b2);
    }
    // 3) attention scores + mask
    {
        dim3 grid(LQ / 64, LQ / 64, NB * NH);    // (8, 8, 16)
        attn_kernel<<<grid, 256>>>(q, k, out);
    }
}